// round 1
// baseline (speedup 1.0000x reference)
#include <cuda_runtime.h>
#include <cuda_bf16.h>
#include <math.h>

// ---------------- Problem constants ----------------
#define LAYERS 2
#define D      2048
#define H      16
#define FF     8192
#define BATCH  2
#define SEQ    1024
#define DH     128           // D / H
#define TD     (3 * D)       // qkv width
#define BS     (BATCH * SEQ) // 2048 tokens
#define NEGB   (-1e9f)
#define SCALE  0.08838834764831845f  // 1/sqrt(128)

// ---------------- Scratch (static device globals; no runtime alloc) ----------------
__device__ float g_x   [BS * D];   // residual stream
__device__ float g_h   [BS * D];   // LN output / final hidden
__device__ float g_qkv [BS * TD];  // fused qkv
__device__ float g_ao  [BS * D];   // attention output
__device__ float g_ff  [BS * FF];  // gelu(h @ W1)
__device__ float g_mean[BATCH * D];
__device__ float g_t   [BATCH * D];

// ---------------- Embedding gather ----------------
__global__ void embed_kernel(const int* __restrict__ ids,
                             const float* __restrict__ emb,
                             float* __restrict__ x) {
    int idx = blockIdx.x * blockDim.x + threadIdx.x;   // over BS*D
    int tok = ids[idx / D];
    x[idx] = emb[(size_t)tok * D + (idx % D)];
}

// ---------------- LayerNorm (one block per row, row cached in smem) ----------------
__global__ void ln_kernel(const float* __restrict__ x,
                          const float* __restrict__ g,
                          const float* __restrict__ b,
                          float* __restrict__ out) {
    __shared__ float row[D];
    __shared__ float red[256];
    const int tid = threadIdx.x;
    const float* xr = x + (size_t)blockIdx.x * D;

    float s = 0.f;
    for (int i = tid; i < D; i += 256) { float v = xr[i]; row[i] = v; s += v; }
    red[tid] = s; __syncthreads();
    for (int st = 128; st > 0; st >>= 1) {
        if (tid < st) red[tid] += red[tid + st];
        __syncthreads();
    }
    const float mean = red[0] * (1.0f / D);
    __syncthreads();

    float s2 = 0.f;
    for (int i = tid; i < D; i += 256) { float v = row[i] - mean; s2 += v * v; }
    red[tid] = s2; __syncthreads();
    for (int st = 128; st > 0; st >>= 1) {
        if (tid < st) red[tid] += red[tid + st];
        __syncthreads();
    }
    const float rstd = rsqrtf(red[0] * (1.0f / D) + 1e-5f);

    float* orow = out + (size_t)blockIdx.x * D;
    for (int i = tid; i < D; i += 256)
        orow[i] = (row[i] - mean) * rstd * g[i] + b[i];
}

// ---------------- SGEMM: C[M,N] = A[M,K] @ B[K,N] (+epilogue) ----------------
// EPI: 0 = plain store, 1 = residual add (C += A@B), 2 = tanh-gelu
// Requires M%128==0, N%128==0, K%8==0 (true for all uses here).
template<int EPI>
__global__ void __launch_bounds__(256)
sgemm_kernel(const float* __restrict__ A, const float* __restrict__ B,
             float* __restrict__ C, int M, int N, int K) {
    __shared__ float As[8][128];
    __shared__ float Bs[8][128];
    const int tid = threadIdx.x;
    const int tx = tid & 15;          // 0..15
    const int ty = tid >> 4;          // 0..15
    const int rowBase = blockIdx.y * 128;
    const int colBase = blockIdx.x * 128;

    const int aRow = tid >> 1;        // 0..127
    const int aCol = (tid & 1) * 4;   // 0 or 4
    const int bRow = tid >> 5;        // 0..7
    const int bCol = (tid & 31) * 4;  // 0..124

    const float* Ag = A + (size_t)(rowBase + aRow) * K + aCol;
    const float* Bg = B + (size_t)bRow * N + colBase + bCol;

    float acc[8][8];
    #pragma unroll
    for (int i = 0; i < 8; i++)
        #pragma unroll
        for (int j = 0; j < 8; j++) acc[i][j] = 0.f;

    for (int k0 = 0; k0 < K; k0 += 8) {
        float4 av = *(const float4*)(Ag + k0);
        float4 bv = *(const float4*)(Bg + (size_t)k0 * N);
        As[aCol + 0][aRow] = av.x;
        As[aCol + 1][aRow] = av.y;
        As[aCol + 2][aRow] = av.z;
        As[aCol + 3][aRow] = av.w;
        *(float4*)&Bs[bRow][bCol] = bv;
        __syncthreads();

        #pragma unroll
        for (int kk = 0; kk < 8; kk++) {
            float a[8], bb[8];
            *(float4*)(a)      = *(const float4*)&As[kk][ty * 8];
            *(float4*)(a + 4)  = *(const float4*)&As[kk][ty * 8 + 4];
            *(float4*)(bb)     = *(const float4*)&Bs[kk][tx * 8];
            *(float4*)(bb + 4) = *(const float4*)&Bs[kk][tx * 8 + 4];
            #pragma unroll
            for (int i = 0; i < 8; i++)
                #pragma unroll
                for (int j = 0; j < 8; j++)
                    acc[i][j] = fmaf(a[i], bb[j], acc[i][j]);
        }
        __syncthreads();
    }

    #pragma unroll
    for (int i = 0; i < 8; i++) {
        size_t r = (size_t)(rowBase + ty * 8 + i);
        float* Cr = C + r * N + colBase + tx * 8;
        #pragma unroll
        for (int j = 0; j < 8; j++) {
            float v = acc[i][j];
            if (EPI == 1) v += Cr[j];
            if (EPI == 2) {
                float xx = v;
                v = 0.5f * xx * (1.0f + tanhf(0.7978845608028654f *
                                              (xx + 0.044715f * xx * xx * xx)));
            }
            Cr[j] = v;
        }
    }
}

// ---------------- Fused causal attention: one block per (b,h,q) row ----------------
__global__ void attn_kernel(const float* __restrict__ qkv,
                            const int* __restrict__ mask,
                            float* __restrict__ o) {
    const int tid = threadIdx.x;          // 0..127
    const int q = blockIdx.x % SEQ;
    const int h = (blockIdx.x / SEQ) % H;
    const int b = blockIdx.x / (SEQ * H);

    __shared__ float qs[DH];
    __shared__ float p[SEQ];
    __shared__ float red[128];

    const size_t base = (size_t)b * SEQ * TD;
    qs[tid] = qkv[base + (size_t)q * TD + h * DH + tid];
    __syncthreads();

    // scores for j <= q (causal); softmax over them (j > q contributes exactly 0)
    float lmax = -1e30f;
    for (int j = tid; j <= q; j += 128) {
        const float* kp = qkv + base + (size_t)j * TD + D + h * DH;
        float dot = 0.f;
        #pragma unroll
        for (int d = 0; d < DH; d += 4) {
            float4 kv4 = *(const float4*)(kp + d);
            dot = fmaf(kv4.x, qs[d],     dot);
            dot = fmaf(kv4.y, qs[d + 1], dot);
            dot = fmaf(kv4.z, qs[d + 2], dot);
            dot = fmaf(kv4.w, qs[d + 3], dot);
        }
        float sc = dot * SCALE;
        if (mask[b * SEQ + j] == 0) sc += NEGB;
        p[j] = sc;
        lmax = fmaxf(lmax, sc);
    }
    red[tid] = lmax; __syncthreads();
    for (int st = 64; st > 0; st >>= 1) {
        if (tid < st) red[tid] = fmaxf(red[tid], red[tid + st]);
        __syncthreads();
    }
    const float mx = red[0];
    __syncthreads();

    float ls = 0.f;
    for (int j = tid; j <= q; j += 128) {
        float e = expf(p[j] - mx);
        p[j] = e;
        ls += e;
    }
    red[tid] = ls; __syncthreads();
    for (int st = 64; st > 0; st >>= 1) {
        if (tid < st) red[tid] += red[tid + st];
        __syncthreads();
    }
    const float inv = 1.0f / red[0];

    // o[d] = sum_j p[j] * v[j][d] ; d = tid (coalesced v reads)
    float acc = 0.f;
    const float* vb = qkv + base + 2 * D + h * DH + tid;
    int j = 0;
    const int qe = q + 1;
    #pragma unroll 4
    for (; j < qe; j++)
        acc = fmaf(p[j], vb[(size_t)j * TD], acc);
    o[((size_t)(b * SEQ + q)) * D + h * DH + tid] = acc * inv;
}

// ---------------- Masked mean pool over sequence ----------------
__global__ void meanpool_kernel(const float* __restrict__ hs,
                                const int* __restrict__ mask,
                                float* __restrict__ mean) {
    int idx = blockIdx.x * blockDim.x + threadIdx.x;  // over BATCH*D
    int b = idx / D;
    int d = idx % D;
    float acc = 0.f, msum = 0.f;
    const float* hb = hs + (size_t)b * SEQ * D + d;
    const int* mb = mask + b * SEQ;
    for (int s = 0; s < SEQ; s++) {
        float mf = (float)mb[s];
        acc = fmaf(mf, hb[(size_t)s * D], acc);
        msum += mf;
    }
    mean[idx] = acc / fmaxf(msum, 1e-9f);
}

// ---------------- Head stage 1: t = tanh(mean @ Wc1 + bc1) ----------------
__global__ void head1_kernel(const float* __restrict__ mean,
                             const float* __restrict__ Wc1,
                             const float* __restrict__ bc1,
                             float* __restrict__ t) {
    int idx = blockIdx.x * blockDim.x + threadIdx.x;  // over BATCH*D
    int b = idx / D;
    int j = idx % D;
    float acc = bc1[j];
    const float* mb = mean + (size_t)b * D;
    for (int k = 0; k < D; k++)
        acc = fmaf(mb[k], Wc1[(size_t)k * D + j], acc);
    t[idx] = tanhf(acc);
}

// ---------------- Head stage 2: logits + softmax[:,1] ----------------
__global__ void head2_kernel(const float* __restrict__ t,
                             const float* __restrict__ Wc2,
                             const float* __restrict__ bc2,
                             float* __restrict__ out) {
    __shared__ float red[256];
    __shared__ float logits[4];
    const int tid = threadIdx.x;
    float part[4] = {0.f, 0.f, 0.f, 0.f};
    for (int j = tid; j < D; j += 256) {
        float t0 = t[j], t1 = t[D + j];
        float w0 = Wc2[2 * j], w1 = Wc2[2 * j + 1];
        part[0] = fmaf(t0, w0, part[0]);
        part[1] = fmaf(t0, w1, part[1]);
        part[2] = fmaf(t1, w0, part[2]);
        part[3] = fmaf(t1, w1, part[3]);
    }
    for (int c = 0; c < 4; c++) {
        __syncthreads();
        red[tid] = part[c]; __syncthreads();
        for (int st = 128; st > 0; st >>= 1) {
            if (tid < st) red[tid] += red[tid + st];
            __syncthreads();
        }
        if (tid == 0) logits[c] = red[0] + bc2[c & 1];
    }
    __syncthreads();
    if (tid == 0) {
        for (int b = 0; b < BATCH; b++) {
            float l0 = logits[2 * b], l1 = logits[2 * b + 1];
            float m = fmaxf(l0, l1);
            float e0 = expf(l0 - m), e1 = expf(l1 - m);
            out[b] = e1 / (e0 + e1);
        }
    }
}

// ---------------- Launch ----------------
extern "C" void kernel_launch(void* const* d_in, const int* in_sizes, int n_in,
                              void* d_out, int out_size) {
    const int*   ids   = (const int*)d_in[0];
    const int*   amask = (const int*)d_in[1];
    const float* emb   = (const float*)d_in[2];
    const float* ln1_g = (const float*)d_in[3];
    const float* ln1_b = (const float*)d_in[4];
    const float* Wqkv  = (const float*)d_in[5];
    const float* Wo    = (const float*)d_in[6];
    const float* ln2_g = (const float*)d_in[7];
    const float* ln2_b = (const float*)d_in[8];
    const float* W1    = (const float*)d_in[9];
    const float* W2    = (const float*)d_in[10];
    const float* lnf_g = (const float*)d_in[11];
    const float* lnf_b = (const float*)d_in[12];
    const float* Wc1   = (const float*)d_in[13];
    const float* bc1   = (const float*)d_in[14];
    const float* Wc2   = (const float*)d_in[15];
    const float* bc2   = (const float*)d_in[16];
    float* out = (float*)d_out;

    float *x, *h, *qkv, *ao, *ff, *mean, *t;
    cudaGetSymbolAddress((void**)&x,    g_x);
    cudaGetSymbolAddress((void**)&h,    g_h);
    cudaGetSymbolAddress((void**)&qkv,  g_qkv);
    cudaGetSymbolAddress((void**)&ao,   g_ao);
    cudaGetSymbolAddress((void**)&ff,   g_ff);
    cudaGetSymbolAddress((void**)&mean, g_mean);
    cudaGetSymbolAddress((void**)&t,    g_t);

    embed_kernel<<<(BS * D) / 256, 256>>>(ids, emb, x);

    for (int l = 0; l < LAYERS; l++) {
        ln_kernel<<<BS, 256>>>(x, ln1_g + (size_t)l * D, ln1_b + (size_t)l * D, h);
        sgemm_kernel<0><<<dim3(TD / 128, BS / 128), 256>>>(
            h, Wqkv + (size_t)l * D * TD, qkv, BS, TD, D);
        attn_kernel<<<BATCH * H * SEQ, 128>>>(qkv, amask, ao);
        sgemm_kernel<1><<<dim3(D / 128, BS / 128), 256>>>(
            ao, Wo + (size_t)l * D * D, x, BS, D, D);
        ln_kernel<<<BS, 256>>>(x, ln2_g + (size_t)l * D, ln2_b + (size_t)l * D, h);
        sgemm_kernel<2><<<dim3(FF / 128, BS / 128), 256>>>(
            h, W1 + (size_t)l * D * FF, ff, BS, FF, D);
        sgemm_kernel<1><<<dim3(D / 128, BS / 128), 256>>>(
            ff, W2 + (size_t)l * FF * D, x, BS, D, FF);
    }

    ln_kernel<<<BS, 256>>>(x, lnf_g, lnf_b, h);
    meanpool_kernel<<<(BATCH * D) / 256, 256>>>(h, amask, mean);
    head1_kernel<<<(BATCH * D) / 256, 256>>>(mean, Wc1, bc1, t);
    head2_kernel<<<1, 256>>>(t, Wc2, bc2, out);
}

// round 2
// speedup vs baseline: 1.5401x; 1.5401x over previous
#include <cuda_runtime.h>
#include <cuda_bf16.h>
#include <math.h>

// ---------------- Problem constants ----------------
#define LAYERS 2
#define D      2048
#define H      16
#define FF     8192
#define BATCH  2
#define SEQ    1024
#define DH     128
#define TD     (3 * D)
#define BS     (BATCH * SEQ)
#define NEGB   (-1e9f)
#define SCALE  0.08838834764831845f

// ---------------- Scratch (static device globals) ----------------
__device__ float g_x   [BS * D];
__device__ float g_h   [BS * D];
__device__ float g_qkv [BS * TD];
__device__ float g_ao  [BS * D];
__device__ float g_ff  [BS * FF];
__device__ float g_mean[BATCH * D];
__device__ float g_t   [BATCH * D];
// bf16 split buffers
__device__ __nv_bfloat16 g_a3   [BS * 3 * FF];   // activations [M][3K], K up to FF
__device__ __nv_bfloat16 g_wqkv3[TD * 3 * D];    // [N=6144][3K=6144]
__device__ __nv_bfloat16 g_wo3  [D  * 3 * D];    // [2048][6144]
__device__ __nv_bfloat16 g_w13  [FF * 3 * D];    // [8192][6144]
__device__ __nv_bfloat16 g_w23  [D  * 3 * FF];   // [2048][24576]

// ---------------- Embedding gather ----------------
__global__ void embed_kernel(const int* __restrict__ ids,
                             const float* __restrict__ emb,
                             float* __restrict__ x) {
    int idx = blockIdx.x * blockDim.x + threadIdx.x;
    int tok = ids[idx / D];
    x[idx] = emb[(size_t)tok * D + (idx % D)];
}

// ---------------- LayerNorm ----------------
__global__ void ln_kernel(const float* __restrict__ x,
                          const float* __restrict__ g,
                          const float* __restrict__ b,
                          float* __restrict__ out) {
    __shared__ float row[D];
    __shared__ float red[256];
    const int tid = threadIdx.x;
    const float* xr = x + (size_t)blockIdx.x * D;

    float s = 0.f;
    for (int i = tid; i < D; i += 256) { float v = xr[i]; row[i] = v; s += v; }
    red[tid] = s; __syncthreads();
    for (int st = 128; st > 0; st >>= 1) {
        if (tid < st) red[tid] += red[tid + st];
        __syncthreads();
    }
    const float mean = red[0] * (1.0f / D);
    __syncthreads();

    float s2 = 0.f;
    for (int i = tid; i < D; i += 256) { float v = row[i] - mean; s2 += v * v; }
    red[tid] = s2; __syncthreads();
    for (int st = 128; st > 0; st >>= 1) {
        if (tid < st) red[tid] += red[tid + st];
        __syncthreads();
    }
    const float rstd = rsqrtf(red[0] * (1.0f / D) + 1e-5f);

    float* orow = out + (size_t)blockIdx.x * D;
    for (int i = tid; i < D; i += 256)
        orow[i] = (row[i] - mean) * rstd * g[i] + b[i];
}

// ---------------- Split-convert activations: X[M,K] fp32 -> X3[M,3K] bf16 ----------------
__global__ void conva_kernel(const float* __restrict__ X,
                             __nv_bfloat16* __restrict__ X3, int K) {
    int idx = blockIdx.x * 256 + threadIdx.x;   // over M*K
    int m = idx / K, k = idx % K;
    float x = X[idx];
    __nv_bfloat16 hi = __float2bfloat16(x);
    __nv_bfloat16 lo = __float2bfloat16(x - __bfloat162float(hi));
    size_t base = (size_t)m * (3 * K);
    X3[base + k]         = hi;
    X3[base + K + k]     = lo;
    X3[base + 2 * K + k] = hi;
}

// ---------------- Split-convert + transpose weights: W[K,N] fp32 -> Wt3[N,3K] bf16 ----------------
__global__ void convw_kernel(const float* __restrict__ W,
                             __nv_bfloat16* __restrict__ Wt3, int K, int N) {
    __shared__ float tile[32][33];
    int n0 = blockIdx.x * 32, k0 = blockIdx.y * 32;
    int tx = threadIdx.x, ty = threadIdx.y;   // (32, 8)
    #pragma unroll
    for (int i = 0; i < 32; i += 8)
        tile[ty + i][tx] = W[(size_t)(k0 + ty + i) * N + n0 + tx];
    __syncthreads();
    #pragma unroll
    for (int i = 0; i < 32; i += 8) {
        int n = n0 + ty + i, k = k0 + tx;
        float x = tile[tx][ty + i];
        __nv_bfloat16 hi = __float2bfloat16(x);
        __nv_bfloat16 lo = __float2bfloat16(x - __bfloat162float(hi));
        size_t base = (size_t)n * (3 * K);
        Wt3[base + k]         = hi;
        Wt3[base + K + k]     = hi;
        Wt3[base + 2 * K + k] = lo;
    }
}

// ---------------- bf16 tensor-core GEMM ----------------
// C[M,N] fp32 = A[M,K3] (row-major bf16) @ Bt[N,K3]^T (bf16), EPI as before.
__device__ __forceinline__ unsigned swz(unsigned o) { return o ^ ((o >> 3) & 0x70); }

__device__ __forceinline__ void ldsm4(unsigned addr, unsigned& r0, unsigned& r1,
                                      unsigned& r2, unsigned& r3) {
    asm volatile("ldmatrix.sync.aligned.m8n8.x4.shared.b16 {%0,%1,%2,%3}, [%4];\n"
                 : "=r"(r0), "=r"(r1), "=r"(r2), "=r"(r3) : "r"(addr));
}
__device__ __forceinline__ void mma16816(float* c, unsigned a0, unsigned a1,
                                         unsigned a2, unsigned a3,
                                         unsigned b0, unsigned b1) {
    asm volatile(
        "mma.sync.aligned.m16n8k16.row.col.f32.bf16.bf16.f32 "
        "{%0,%1,%2,%3},{%4,%5,%6,%7},{%8,%9},{%0,%1,%2,%3};\n"
        : "+f"(c[0]), "+f"(c[1]), "+f"(c[2]), "+f"(c[3])
        : "r"(a0), "r"(a1), "r"(a2), "r"(a3), "r"(b0), "r"(b1));
}
__device__ __forceinline__ void cpasync16(unsigned saddr, const void* g) {
    asm volatile("cp.async.cg.shared.global [%0], [%1], 16;\n" :: "r"(saddr), "l"(g));
}

// load 128-row x 32-col bf16 tile into paired-row swizzled smem (8KB)
__device__ __forceinline__ void load_tile(const __nv_bfloat16* gbase, unsigned sbase,
                                          int ld, int k0) {
    int t = threadIdx.x;
    #pragma unroll
    for (int i = 0; i < 2; i++) {
        int c = t + i * 256;            // 0..511
        int row = c >> 2, seg = c & 3;  // 4x16B per 64B row
        unsigned so = swz((unsigned)((row >> 1) * 128 + (row & 1) * 64 + seg * 16));
        cpasync16(sbase + so, gbase + (size_t)row * ld + k0 + seg * 8);
    }
}

__device__ __forceinline__ float gelu_f(float xx) {
    return 0.5f * xx * (1.0f + tanhf(0.7978845608028654f *
                                     (xx + 0.044715f * xx * xx * xx)));
}

template<int EPI>
__global__ void __launch_bounds__(256)
bgemm_kernel(const __nv_bfloat16* __restrict__ A,
             const __nv_bfloat16* __restrict__ Bt,
             float* __restrict__ C, int M, int N, int K3) {
    __shared__ __align__(1024) __nv_bfloat16 sA[2][128 * 32];
    __shared__ __align__(1024) __nv_bfloat16 sB[2][128 * 32];
    const int tid = threadIdx.x, lane = tid & 31, warp = tid >> 5;
    const int warpM = warp & 1, warpN = warp >> 1;   // 2 x 4 warp grid
    const int rowBase = blockIdx.y * 128, colBase = blockIdx.x * 128;
    const __nv_bfloat16* Ab = A  + (size_t)rowBase * K3;
    const __nv_bfloat16* Bb = Bt + (size_t)colBase * K3;
    unsigned aBase = (unsigned)__cvta_generic_to_shared(&sA[0][0]);
    unsigned bBase = (unsigned)__cvta_generic_to_shared(&sB[0][0]);

    float acc[4][4][4];
    #pragma unroll
    for (int i = 0; i < 4; i++)
        #pragma unroll
        for (int j = 0; j < 4; j++)
            #pragma unroll
            for (int r = 0; r < 4; r++) acc[i][j][r] = 0.f;

    const int KT = K3 >> 5;
    load_tile(Ab, aBase, K3, 0);
    load_tile(Bb, bBase, K3, 0);
    asm volatile("cp.async.commit_group;\n");

    for (int kt = 0; kt < KT; kt++) {
        int buf = kt & 1;
        if (kt + 1 < KT) {
            load_tile(Ab, aBase + (unsigned)(buf ^ 1) * 8192, K3, (kt + 1) << 5);
            load_tile(Bb, bBase + (unsigned)(buf ^ 1) * 8192, K3, (kt + 1) << 5);
            asm volatile("cp.async.commit_group;\n");
            asm volatile("cp.async.wait_group 1;\n");
        } else {
            asm volatile("cp.async.wait_group 0;\n");
        }
        __syncthreads();

        unsigned aS = aBase + (unsigned)buf * 8192;
        unsigned bS = bBase + (unsigned)buf * 8192;
        #pragma unroll
        for (int ks = 0; ks < 2; ks++) {
            unsigned a[4][4], b[2][4];
            #pragma unroll
            for (int mi = 0; mi < 4; mi++) {
                int row = warpM * 64 + mi * 16 + (lane & 15);
                unsigned byte = (unsigned)((row >> 1) * 128 + (row & 1) * 64 +
                                           ks * 32 + (lane >> 4) * 16);
                ldsm4(aS + swz(byte), a[mi][0], a[mi][1], a[mi][2], a[mi][3]);
            }
            #pragma unroll
            for (int np = 0; np < 2; np++) {
                int rown = warpN * 32 + np * 16 + (lane & 15);
                unsigned byte = (unsigned)((rown >> 1) * 128 + (rown & 1) * 64 +
                                           ks * 32 + (lane >> 4) * 16);
                ldsm4(bS + swz(byte), b[np][0], b[np][1], b[np][2], b[np][3]);
            }
            #pragma unroll
            for (int mi = 0; mi < 4; mi++)
                #pragma unroll
                for (int ni = 0; ni < 4; ni++) {
                    unsigned b0 = b[ni >> 1][(ni & 1)];
                    unsigned b1 = b[ni >> 1][2 + (ni & 1)];
                    mma16816(acc[mi][ni], a[mi][0], a[mi][1], a[mi][2], a[mi][3], b0, b1);
                }
        }
        __syncthreads();
    }

    // epilogue
    #pragma unroll
    for (int mi = 0; mi < 4; mi++)
        #pragma unroll
        for (int ni = 0; ni < 4; ni++) {
            int row = rowBase + warpM * 64 + mi * 16 + (lane >> 2);
            int col = colBase + warpN * 32 + ni * 8 + 2 * (lane & 3);
            float* p = C + (size_t)row * N + col;
            float* q = C + (size_t)(row + 8) * N + col;
            float v0 = acc[mi][ni][0], v1 = acc[mi][ni][1];
            float v2 = acc[mi][ni][2], v3 = acc[mi][ni][3];
            if (EPI == 1) { v0 += p[0]; v1 += p[1]; v2 += q[0]; v3 += q[1]; }
            if (EPI == 2) { v0 = gelu_f(v0); v1 = gelu_f(v1); v2 = gelu_f(v2); v3 = gelu_f(v3); }
            float2 w0 = make_float2(v0, v1);
            float2 w1 = make_float2(v2, v3);
            *(float2*)p = w0;
            *(float2*)q = w1;
        }
}

// ---------------- Fused causal attention (unchanged) ----------------
__global__ void attn_kernel(const float* __restrict__ qkv,
                            const int* __restrict__ mask,
                            float* __restrict__ o) {
    const int tid = threadIdx.x;
    const int q = blockIdx.x % SEQ;
    const int h = (blockIdx.x / SEQ) % H;
    const int b = blockIdx.x / (SEQ * H);

    __shared__ float qs[DH];
    __shared__ float p[SEQ];
    __shared__ float red[128];

    const size_t base = (size_t)b * SEQ * TD;
    qs[tid] = qkv[base + (size_t)q * TD + h * DH + tid];
    __syncthreads();

    float lmax = -1e30f;
    for (int j = tid; j <= q; j += 128) {
        const float* kp = qkv + base + (size_t)j * TD + D + h * DH;
        float dot = 0.f;
        #pragma unroll
        for (int d = 0; d < DH; d += 4) {
            float4 kv4 = *(const float4*)(kp + d);
            dot = fmaf(kv4.x, qs[d],     dot);
            dot = fmaf(kv4.y, qs[d + 1], dot);
            dot = fmaf(kv4.z, qs[d + 2], dot);
            dot = fmaf(kv4.w, qs[d + 3], dot);
        }
        float sc = dot * SCALE;
        if (mask[b * SEQ + j] == 0) sc += NEGB;
        p[j] = sc;
        lmax = fmaxf(lmax, sc);
    }
    red[tid] = lmax; __syncthreads();
    for (int st = 64; st > 0; st >>= 1) {
        if (tid < st) red[tid] = fmaxf(red[tid], red[tid + st]);
        __syncthreads();
    }
    const float mx = red[0];
    __syncthreads();

    float ls = 0.f;
    for (int j = tid; j <= q; j += 128) {
        float e = expf(p[j] - mx);
        p[j] = e;
        ls += e;
    }
    red[tid] = ls; __syncthreads();
    for (int st = 64; st > 0; st >>= 1) {
        if (tid < st) red[tid] += red[tid + st];
        __syncthreads();
    }
    const float inv = 1.0f / red[0];

    float acc = 0.f;
    const float* vb = qkv + base + 2 * D + h * DH + tid;
    const int qe = q + 1;
    #pragma unroll 4
    for (int j = 0; j < qe; j++)
        acc = fmaf(p[j], vb[(size_t)j * TD], acc);
    o[((size_t)(b * SEQ + q)) * D + h * DH + tid] = acc * inv;
}

// ---------------- Pool + head ----------------
__global__ void meanpool_kernel(const float* __restrict__ hs,
                                const int* __restrict__ mask,
                                float* __restrict__ mean) {
    int idx = blockIdx.x * blockDim.x + threadIdx.x;
    int b = idx / D;
    int d = idx % D;
    float acc = 0.f, msum = 0.f;
    const float* hb = hs + (size_t)b * SEQ * D + d;
    const int* mb = mask + b * SEQ;
    for (int s = 0; s < SEQ; s++) {
        float mf = (float)mb[s];
        acc = fmaf(mf, hb[(size_t)s * D], acc);
        msum += mf;
    }
    mean[idx] = acc / fmaxf(msum, 1e-9f);
}

__global__ void head1_kernel(const float* __restrict__ mean,
                             const float* __restrict__ Wc1,
                             const float* __restrict__ bc1,
                             float* __restrict__ t) {
    int idx = blockIdx.x * blockDim.x + threadIdx.x;
    int b = idx / D;
    int j = idx % D;
    float acc = bc1[j];
    const float* mb = mean + (size_t)b * D;
    for (int k = 0; k < D; k++)
        acc = fmaf(mb[k], Wc1[(size_t)k * D + j], acc);
    t[idx] = tanhf(acc);
}

__global__ void head2_kernel(const float* __restrict__ t,
                             const float* __restrict__ Wc2,
                             const float* __restrict__ bc2,
                             float* __restrict__ out) {
    __shared__ float red[256];
    __shared__ float logits[4];
    const int tid = threadIdx.x;
    float part[4] = {0.f, 0.f, 0.f, 0.f};
    for (int j = tid; j < D; j += 256) {
        float t0 = t[j], t1 = t[D + j];
        float w0 = Wc2[2 * j], w1 = Wc2[2 * j + 1];
        part[0] = fmaf(t0, w0, part[0]);
        part[1] = fmaf(t0, w1, part[1]);
        part[2] = fmaf(t1, w0, part[2]);
        part[3] = fmaf(t1, w1, part[3]);
    }
    for (int c = 0; c < 4; c++) {
        __syncthreads();
        red[tid] = part[c]; __syncthreads();
        for (int st = 128; st > 0; st >>= 1) {
            if (tid < st) red[tid] += red[tid + st];
            __syncthreads();
        }
        if (tid == 0) logits[c] = red[0] + bc2[c & 1];
    }
    __syncthreads();
    if (tid == 0) {
        for (int b = 0; b < BATCH; b++) {
            float l0 = logits[2 * b], l1 = logits[2 * b + 1];
            float m = fmaxf(l0, l1);
            float e0 = expf(l0 - m), e1 = expf(l1 - m);
            out[b] = e1 / (e0 + e1);
        }
    }
}

// ---------------- Launch ----------------
extern "C" void kernel_launch(void* const* d_in, const int* in_sizes, int n_in,
                              void* d_out, int out_size) {
    const int*   ids   = (const int*)d_in[0];
    const int*   amask = (const int*)d_in[1];
    const float* emb   = (const float*)d_in[2];
    const float* ln1_g = (const float*)d_in[3];
    const float* ln1_b = (const float*)d_in[4];
    const float* Wqkv  = (const float*)d_in[5];
    const float* Wo    = (const float*)d_in[6];
    const float* ln2_g = (const float*)d_in[7];
    const float* ln2_b = (const float*)d_in[8];
    const float* W1    = (const float*)d_in[9];
    const float* W2    = (const float*)d_in[10];
    const float* lnf_g = (const float*)d_in[11];
    const float* lnf_b = (const float*)d_in[12];
    const float* Wc1   = (const float*)d_in[13];
    const float* bc1   = (const float*)d_in[14];
    const float* Wc2   = (const float*)d_in[15];
    const float* bc2   = (const float*)d_in[16];
    float* out = (float*)d_out;

    float *x, *h, *qkv, *ao, *ff, *mean, *t;
    __nv_bfloat16 *a3, *wqkv3, *wo3, *w13, *w23;
    cudaGetSymbolAddress((void**)&x,    g_x);
    cudaGetSymbolAddress((void**)&h,    g_h);
    cudaGetSymbolAddress((void**)&qkv,  g_qkv);
    cudaGetSymbolAddress((void**)&ao,   g_ao);
    cudaGetSymbolAddress((void**)&ff,   g_ff);
    cudaGetSymbolAddress((void**)&mean, g_mean);
    cudaGetSymbolAddress((void**)&t,    g_t);
    cudaGetSymbolAddress((void**)&a3,    g_a3);
    cudaGetSymbolAddress((void**)&wqkv3, g_wqkv3);
    cudaGetSymbolAddress((void**)&wo3,   g_wo3);
    cudaGetSymbolAddress((void**)&w13,   g_w13);
    cudaGetSymbolAddress((void**)&w23,   g_w23);

    embed_kernel<<<(BS * D) / 256, 256>>>(ids, emb, x);

    for (int l = 0; l < LAYERS; l++) {
        // attn block
        ln_kernel<<<BS, 256>>>(x, ln1_g + (size_t)l * D, ln1_b + (size_t)l * D, h);
        conva_kernel<<<(BS * D) / 256, 256>>>(h, a3, D);
        convw_kernel<<<dim3(TD / 32, D / 32), dim3(32, 8)>>>(
            Wqkv + (size_t)l * D * TD, wqkv3, D, TD);
        bgemm_kernel<0><<<dim3(TD / 128, BS / 128), 256>>>(
            a3, wqkv3, qkv, BS, TD, 3 * D);
        attn_kernel<<<BATCH * H * SEQ, 128>>>(qkv, amask, ao);
        conva_kernel<<<(BS * D) / 256, 256>>>(ao, a3, D);
        convw_kernel<<<dim3(D / 32, D / 32), dim3(32, 8)>>>(
            Wo + (size_t)l * D * D, wo3, D, D);
        bgemm_kernel<1><<<dim3(D / 128, BS / 128), 256>>>(
            a3, wo3, x, BS, D, 3 * D);
        // mlp block
        ln_kernel<<<BS, 256>>>(x, ln2_g + (size_t)l * D, ln2_b + (size_t)l * D, h);
        conva_kernel<<<(BS * D) / 256, 256>>>(h, a3, D);
        convw_kernel<<<dim3(FF / 32, D / 32), dim3(32, 8)>>>(
            W1 + (size_t)l * D * FF, w13, D, FF);
        bgemm_kernel<2><<<dim3(FF / 128, BS / 128), 256>>>(
            a3, w13, ff, BS, FF, 3 * D);
        conva_kernel<<<(BS * FF) / 256, 256>>>(ff, a3, FF);
        convw_kernel<<<dim3(D / 32, FF / 32), dim3(32, 8)>>>(
            W2 + (size_t)l * FF * D, w23, FF, D);
        bgemm_kernel<1><<<dim3(D / 128, BS / 128), 256>>>(
            a3, w23, x, BS, D, 3 * FF);
    }

    ln_kernel<<<BS, 256>>>(x, lnf_g, lnf_b, h);
    meanpool_kernel<<<(BATCH * D) / 256, 256>>>(h, amask, mean);
    head1_kernel<<<(BATCH * D) / 256, 256>>>(mean, Wc1, bc1, t);
    head2_kernel<<<1, 256>>>(t, Wc2, bc2, out);
}

// round 4
// speedup vs baseline: 2.9025x; 1.8846x over previous
#include <cuda_runtime.h>
#include <cuda_bf16.h>
#include <math.h>
#include <stdint.h>

// ---------------- Problem constants ----------------
#define LAYERS 2
#define D      2048
#define H      16
#define FF     8192
#define BATCH  2
#define SEQ    1024
#define DH     128
#define TD     (3 * D)
#define BS     (BATCH * SEQ)
#define NEGB   (-1e9f)
#define SCALE  0.08838834764831845f

// ---------------- Scratch (static device globals) ----------------
__device__ float g_x   [BS * D];
__device__ float g_h   [BS * D];
__device__ float g_qkv [BS * TD];
__device__ float g_mean[BATCH * D];
__device__ float g_t   [BATCH * D];
// bf16x3 split buffers
__device__ __nv_bfloat16 g_a3s  [BS * 3 * D];    // activations, K=D
__device__ __nv_bfloat16 g_a3f  [BS * 3 * FF];   // activations, K=FF
__device__ __nv_bfloat16 g_wqkv3[TD * 3 * D];
__device__ __nv_bfloat16 g_wo3  [D  * 3 * D];
__device__ __nv_bfloat16 g_w13  [FF * 3 * D];
__device__ __nv_bfloat16 g_w23  [D  * 3 * FF];

// ---------------- Embedding gather ----------------
__global__ void embed_kernel(const int* __restrict__ ids,
                             const float* __restrict__ emb,
                             float* __restrict__ x) {
    int idx = blockIdx.x * blockDim.x + threadIdx.x;
    int tok = ids[idx / D];
    x[idx] = emb[(size_t)tok * D + (idx % D)];
}

// ---------------- LayerNorm; SPLIT=1 writes bf16x3 (K=D), else fp32 ----------------
template<int SPLIT>
__global__ void ln_kernel(const float* __restrict__ x,
                          const float* __restrict__ g,
                          const float* __restrict__ b,
                          float* __restrict__ outf,
                          __nv_bfloat16* __restrict__ out3) {
    __shared__ float row[D];
    __shared__ float red[256];
    const int tid = threadIdx.x;
    const float* xr = x + (size_t)blockIdx.x * D;

    float s = 0.f;
    for (int i = tid; i < D; i += 256) { float v = xr[i]; row[i] = v; s += v; }
    red[tid] = s; __syncthreads();
    for (int st = 128; st > 0; st >>= 1) {
        if (tid < st) red[tid] += red[tid + st];
        __syncthreads();
    }
    const float mean = red[0] * (1.0f / D);
    __syncthreads();

    float s2 = 0.f;
    for (int i = tid; i < D; i += 256) { float v = row[i] - mean; s2 += v * v; }
    red[tid] = s2; __syncthreads();
    for (int st = 128; st > 0; st >>= 1) {
        if (tid < st) red[tid] += red[tid + st];
        __syncthreads();
    }
    const float rstd = rsqrtf(red[0] * (1.0f / D) + 1e-5f);

    if (SPLIT) {
        __nv_bfloat16* o3 = out3 + (size_t)blockIdx.x * (3 * D);
        for (int i = tid; i < D; i += 256) {
            float v = (row[i] - mean) * rstd * g[i] + b[i];
            __nv_bfloat16 hi = __float2bfloat16(v);
            __nv_bfloat16 lo = __float2bfloat16(v - __bfloat162float(hi));
            o3[i]         = hi;
            o3[D + i]     = lo;
            o3[2 * D + i] = hi;
        }
    } else {
        float* orow = outf + (size_t)blockIdx.x * D;
        for (int i = tid; i < D; i += 256)
            orow[i] = (row[i] - mean) * rstd * g[i] + b[i];
    }
}

// ---------------- Split-convert + transpose weights: W[K,N] fp32 -> Wt3[N,3K] bf16 ----------------
__global__ void convw_kernel(const float* __restrict__ W,
                             __nv_bfloat16* __restrict__ Wt3, int K, int N) {
    __shared__ float tile[32][33];
    int n0 = blockIdx.x * 32, k0 = blockIdx.y * 32;
    int tx = threadIdx.x, ty = threadIdx.y;
    #pragma unroll
    for (int i = 0; i < 32; i += 8)
        tile[ty + i][tx] = W[(size_t)(k0 + ty + i) * N + n0 + tx];
    __syncthreads();
    #pragma unroll
    for (int i = 0; i < 32; i += 8) {
        int n = n0 + ty + i, k = k0 + tx;
        float x = tile[tx][ty + i];
        __nv_bfloat16 hi = __float2bfloat16(x);
        __nv_bfloat16 lo = __float2bfloat16(x - __bfloat162float(hi));
        size_t base = (size_t)n * (3 * K);
        Wt3[base + k]         = hi;
        Wt3[base + K + k]     = hi;
        Wt3[base + 2 * K + k] = lo;
    }
}

// ================= mma.sync bf16 GEMM, 4-stage cp.async =================
// C[M,N] fp32 = A[M,K3] bf16 row-major @ Bt[N,K3]^T
// EPI: 0 = store f32, 1 = residual add f32, 2 = gelu -> bf16x3 split into A3out
#define BG_STAGES 4
#define BG_STAGE  16384                 // 8KB A + 8KB B
#define BG_SMEM   (BG_STAGES * BG_STAGE)

__device__ __forceinline__ unsigned swz(unsigned o) { return o ^ ((o >> 3) & 0x70); }

__device__ __forceinline__ void ldsm4(unsigned addr, unsigned& r0, unsigned& r1,
                                      unsigned& r2, unsigned& r3) {
    asm volatile("ldmatrix.sync.aligned.m8n8.x4.shared.b16 {%0,%1,%2,%3}, [%4];\n"
                 : "=r"(r0), "=r"(r1), "=r"(r2), "=r"(r3) : "r"(addr));
}
__device__ __forceinline__ void mma16816(float* c, unsigned a0, unsigned a1,
                                         unsigned a2, unsigned a3,
                                         unsigned b0, unsigned b1) {
    asm volatile(
        "mma.sync.aligned.m16n8k16.row.col.f32.bf16.bf16.f32 "
        "{%0,%1,%2,%3},{%4,%5,%6,%7},{%8,%9},{%0,%1,%2,%3};\n"
        : "+f"(c[0]), "+f"(c[1]), "+f"(c[2]), "+f"(c[3])
        : "r"(a0), "r"(a1), "r"(a2), "r"(a3), "r"(b0), "r"(b1));
}
__device__ __forceinline__ void cpasync16(unsigned saddr, const void* g) {
    asm volatile("cp.async.cg.shared.global [%0], [%1], 16;\n" :: "r"(saddr), "l"(g));
}

// load one 128-row x 32-col bf16 tile into paired-row swizzled smem (8KB)
__device__ __forceinline__ void load_tile(const __nv_bfloat16* gbase, unsigned sbase,
                                          int ld, int k0) {
    int t = threadIdx.x;
    #pragma unroll
    for (int i = 0; i < 2; i++) {
        int c = t + i * 256;
        int row = c >> 2, seg = c & 3;
        unsigned so = swz((unsigned)((row >> 1) * 128 + (row & 1) * 64 + seg * 16));
        cpasync16(sbase + so, gbase + (size_t)row * ld + k0 + seg * 8);
    }
}

__device__ __forceinline__ float gelu_f(float xx) {
    return 0.5f * xx * (1.0f + tanhf(0.7978845608028654f *
                                     (xx + 0.044715f * xx * xx * xx)));
}
__device__ __forceinline__ __nv_bfloat162 hi2(float a, float b) {
    __nv_bfloat162 r;
    r.x = __float2bfloat16(a); r.y = __float2bfloat16(b);
    return r;
}
__device__ __forceinline__ __nv_bfloat162 lo2(float a, float b, __nv_bfloat162 h) {
    __nv_bfloat162 r;
    r.x = __float2bfloat16(a - __bfloat162float(h.x));
    r.y = __float2bfloat16(b - __bfloat162float(h.y));
    return r;
}

template<int EPI>
__global__ void __launch_bounds__(256, 2)
bgemm_kernel(const __nv_bfloat16* __restrict__ A,
             const __nv_bfloat16* __restrict__ Bt,
             float* __restrict__ C,
             __nv_bfloat16* __restrict__ A3out,
             int M, int N, int K3) {
    extern __shared__ __align__(128) char smem[];
    unsigned sbase = (unsigned)__cvta_generic_to_shared(smem);

    const int tid = threadIdx.x, lane = tid & 31, warp = tid >> 5;
    const int warpM = warp & 1, warpN = warp >> 1;
    const int rowBase = blockIdx.x * 128;       // M fastest for B-slab L2 reuse
    const int colBase = blockIdx.y * 128;
    const __nv_bfloat16* Ab = A  + (size_t)rowBase * K3;
    const __nv_bfloat16* Bb = Bt + (size_t)colBase * K3;

    float acc[4][4][4];
    #pragma unroll
    for (int i = 0; i < 4; i++)
        #pragma unroll
        for (int j = 0; j < 4; j++)
            #pragma unroll
            for (int r = 0; r < 4; r++) acc[i][j][r] = 0.f;

    const int KT = K3 >> 5;
    #pragma unroll
    for (int s = 0; s < 3; s++) {                 // prologue: 3 stages
        unsigned st = sbase + s * BG_STAGE;
        load_tile(Ab, st, K3, s << 5);
        load_tile(Bb, st + 8192, K3, s << 5);
        asm volatile("cp.async.commit_group;\n");
    }

    for (int kt = 0; kt < KT; kt++) {
        const int buf = kt & 3;
        asm volatile("cp.async.wait_group 2;\n"); // stage kt resident
        __syncthreads();                          // all warps done with kt-1 compute

        const int next = kt + 3;
        if (next < KT) {
            unsigned st = sbase + (unsigned)(next & 3) * BG_STAGE;
            load_tile(Ab, st, K3, next << 5);
            load_tile(Bb, st + 8192, K3, next << 5);
        }
        asm volatile("cp.async.commit_group;\n");

        unsigned aS = sbase + (unsigned)buf * BG_STAGE;
        unsigned bS = aS + 8192;
        #pragma unroll
        for (int ks = 0; ks < 2; ks++) {
            unsigned a[4][4], b[2][4];
            #pragma unroll
            for (int mi = 0; mi < 4; mi++) {
                int row = warpM * 64 + mi * 16 + (lane & 15);
                unsigned byte = (unsigned)((row >> 1) * 128 + (row & 1) * 64 +
                                           ks * 32 + (lane >> 4) * 16);
                ldsm4(aS + swz(byte), a[mi][0], a[mi][1], a[mi][2], a[mi][3]);
            }
            #pragma unroll
            for (int np = 0; np < 2; np++) {
                int rown = warpN * 32 + np * 16 + (lane & 15);
                unsigned byte = (unsigned)((rown >> 1) * 128 + (rown & 1) * 64 +
                                           ks * 32 + (lane >> 4) * 16);
                ldsm4(bS + swz(byte), b[np][0], b[np][1], b[np][2], b[np][3]);
            }
            #pragma unroll
            for (int mi = 0; mi < 4; mi++)
                #pragma unroll
                for (int ni = 0; ni < 4; ni++) {
                    unsigned b0 = b[ni >> 1][(ni & 1)];
                    unsigned b1 = b[ni >> 1][2 + (ni & 1)];
                    mma16816(acc[mi][ni], a[mi][0], a[mi][1], a[mi][2], a[mi][3], b0, b1);
                }
        }
    }

    // epilogue
    #pragma unroll
    for (int mi = 0; mi < 4; mi++)
        #pragma unroll
        for (int ni = 0; ni < 4; ni++) {
            int row = rowBase + warpM * 64 + mi * 16 + (lane >> 2);
            int col = colBase + warpN * 32 + ni * 8 + 2 * (lane & 3);
            float v0 = acc[mi][ni][0], v1 = acc[mi][ni][1];
            float v2 = acc[mi][ni][2], v3 = acc[mi][ni][3];
            if (EPI == 2) {
                v0 = gelu_f(v0); v1 = gelu_f(v1);
                v2 = gelu_f(v2); v3 = gelu_f(v3);
                size_t b0 = (size_t)row * (3 * (size_t)N);
                size_t b1 = (size_t)(row + 8) * (3 * (size_t)N);
                __nv_bfloat162 h01 = hi2(v0, v1), l01 = lo2(v0, v1, h01);
                __nv_bfloat162 h23 = hi2(v2, v3), l23 = lo2(v2, v3, h23);
                *(__nv_bfloat162*)(A3out + b0 + col)         = h01;
                *(__nv_bfloat162*)(A3out + b0 + N + col)     = l01;
                *(__nv_bfloat162*)(A3out + b0 + 2 * N + col) = h01;
                *(__nv_bfloat162*)(A3out + b1 + col)         = h23;
                *(__nv_bfloat162*)(A3out + b1 + N + col)     = l23;
                *(__nv_bfloat162*)(A3out + b1 + 2 * N + col) = h23;
            } else {
                float* p = C + (size_t)row * N + col;
                float* q = C + (size_t)(row + 8) * N + col;
                if (EPI == 1) { v0 += p[0]; v1 += p[1]; v2 += q[0]; v3 += q[1]; }
                *(float2*)p = make_float2(v0, v1);
                *(float2*)q = make_float2(v2, v3);
            }
        }
}

// ---------------- Tiled causal attention ----------------
// Block: 8 warps = 8 consecutive q rows of one (b,h); K/V streamed in 32-key
// chunks through smem; online softmax; output written as bf16x3 split (K=D).
__global__ void __launch_bounds__(256)
attn_kernel(const float* __restrict__ qkv,
            const int* __restrict__ mask,
            __nv_bfloat16* __restrict__ a3) {
    __shared__ float Qs[8][132];
    __shared__ float Kc[32][132];
    __shared__ float Vc[32][132];

    const int tid = threadIdx.x, lane = tid & 31, warp = tid >> 5;
    const int q0 = blockIdx.x * 8;
    const int h  = blockIdx.y;
    const int b  = blockIdx.z;
    const int q  = q0 + warp;
    const size_t base = (size_t)b * SEQ * TD;

    // load 8 q rows
    {
        int r = tid >> 5, c = (tid & 31) * 4;
        *(float4*)&Qs[r][c] = *(const float4*)&qkv[base + (size_t)(q0 + r) * TD + h * DH + c];
    }

    float m = -1e30f, l = 0.f;
    float4 o = make_float4(0.f, 0.f, 0.f, 0.f);
    const int jmax = q0 + 7;

    for (int j0 = 0; j0 <= jmax; j0 += 32) {
        __syncthreads();   // protect previous chunk reads (and Qs on first iter)
        // 256 threads load 32 K rows + 32 V rows (128 floats each)
        #pragma unroll
        for (int i = 0; i < 4; i++) {
            int idx = tid + i * 256;           // 0..1023
            int r = idx >> 5, c = (idx & 31) * 4;
            const float* src = qkv + base + (size_t)(j0 + r) * TD + h * DH + c;
            *(float4*)&Kc[r][c] = *(const float4*)(src + D);
            *(float4*)&Vc[r][c] = *(const float4*)(src + 2 * D);
        }
        __syncthreads();

        const int j = j0 + lane;
        float s = -1e30f;
        if (j <= q) {
            float dot = 0.f;
            #pragma unroll 8
            for (int d = 0; d < DH; d += 4) {
                float4 kv = *(const float4*)&Kc[lane][d];
                float4 qv = *(const float4*)&Qs[warp][d];
                dot = fmaf(kv.x, qv.x, dot);
                dot = fmaf(kv.y, qv.y, dot);
                dot = fmaf(kv.z, qv.z, dot);
                dot = fmaf(kv.w, qv.w, dot);
            }
            s = dot * SCALE;
            if (mask[b * SEQ + j] == 0) s += NEGB;
        }

        float cmax = s;
        #pragma unroll
        for (int off = 16; off > 0; off >>= 1)
            cmax = fmaxf(cmax, __shfl_xor_sync(0xffffffffu, cmax, off));
        float newm = fmaxf(m, cmax);
        float corr = expf(m - newm);
        float p = expf(s - newm);
        float psum = p;
        #pragma unroll
        for (int off = 16; off > 0; off >>= 1)
            psum += __shfl_xor_sync(0xffffffffu, psum, off);
        l = l * corr + psum;
        o.x *= corr; o.y *= corr; o.z *= corr; o.w *= corr;

        #pragma unroll 8
        for (int jj = 0; jj < 32; jj++) {
            float pj = __shfl_sync(0xffffffffu, p, jj);
            float4 v = *(const float4*)&Vc[jj][lane * 4];
            o.x = fmaf(pj, v.x, o.x);
            o.y = fmaf(pj, v.y, o.y);
            o.z = fmaf(pj, v.z, o.z);
            o.w = fmaf(pj, v.w, o.w);
        }
        m = newm;
    }

    const float inv = 1.f / l;
    float v0 = o.x * inv, v1 = o.y * inv, v2 = o.z * inv, v3 = o.w * inv;
    size_t r3 = (size_t)(b * SEQ + q) * (3 * D);
    int col = h * DH + lane * 4;
    __nv_bfloat162 h01 = hi2(v0, v1), l01 = lo2(v0, v1, h01);
    __nv_bfloat162 h23 = hi2(v2, v3), l23 = lo2(v2, v3, h23);
    *(__nv_bfloat162*)(a3 + r3 + col)             = h01;
    *(__nv_bfloat162*)(a3 + r3 + col + 2)         = h23;
    *(__nv_bfloat162*)(a3 + r3 + D + col)         = l01;
    *(__nv_bfloat162*)(a3 + r3 + D + col + 2)     = l23;
    *(__nv_bfloat162*)(a3 + r3 + 2 * D + col)     = h01;
    *(__nv_bfloat162*)(a3 + r3 + 2 * D + col + 2) = h23;
}

// ---------------- Pool + head ----------------
__global__ void meanpool_kernel(const float* __restrict__ hs,
                                const int* __restrict__ mask,
                                float* __restrict__ mean) {
    int idx = blockIdx.x * blockDim.x + threadIdx.x;
    int b = idx / D;
    int d = idx % D;
    float acc = 0.f, msum = 0.f;
    const float* hb = hs + (size_t)b * SEQ * D + d;
    const int* mb = mask + b * SEQ;
    for (int s = 0; s < SEQ; s++) {
        float mf = (float)mb[s];
        acc = fmaf(mf, hb[(size_t)s * D], acc);
        msum += mf;
    }
    mean[idx] = acc / fmaxf(msum, 1e-9f);
}

__global__ void head1_kernel(const float* __restrict__ mean,
                             const float* __restrict__ Wc1,
                             const float* __restrict__ bc1,
                             float* __restrict__ t) {
    int idx = blockIdx.x * blockDim.x + threadIdx.x;
    int b = idx / D;
    int j = idx % D;
    float acc = bc1[j];
    const float* mb = mean + (size_t)b * D;
    for (int k = 0; k < D; k++)
        acc = fmaf(mb[k], Wc1[(size_t)k * D + j], acc);
    t[idx] = tanhf(acc);
}

__global__ void head2_kernel(const float* __restrict__ t,
                             const float* __restrict__ Wc2,
                             const float* __restrict__ bc2,
                             float* __restrict__ out) {
    __shared__ float red[256];
    __shared__ float logits[4];
    const int tid = threadIdx.x;
    float part[4] = {0.f, 0.f, 0.f, 0.f};
    for (int j = tid; j < D; j += 256) {
        float t0 = t[j], t1 = t[D + j];
        float w0 = Wc2[2 * j], w1 = Wc2[2 * j + 1];
        part[0] = fmaf(t0, w0, part[0]);
        part[1] = fmaf(t0, w1, part[1]);
        part[2] = fmaf(t1, w0, part[2]);
        part[3] = fmaf(t1, w1, part[3]);
    }
    for (int c = 0; c < 4; c++) {
        __syncthreads();
        red[tid] = part[c]; __syncthreads();
        for (int st = 128; st > 0; st >>= 1) {
            if (tid < st) red[tid] += red[tid + st];
            __syncthreads();
        }
        if (tid == 0) logits[c] = red[0] + bc2[c & 1];
    }
    __syncthreads();
    if (tid == 0) {
        for (int b = 0; b < BATCH; b++) {
            float l0 = logits[2 * b], l1 = logits[2 * b + 1];
            float m = fmaxf(l0, l1);
            float e0 = expf(l0 - m), e1 = expf(l1 - m);
            out[b] = e1 / (e0 + e1);
        }
    }
}

// ---------------- Launch ----------------
extern "C" void kernel_launch(void* const* d_in, const int* in_sizes, int n_in,
                              void* d_out, int out_size) {
    const int*   ids   = (const int*)d_in[0];
    const int*   amask = (const int*)d_in[1];
    const float* emb   = (const float*)d_in[2];
    const float* ln1_g = (const float*)d_in[3];
    const float* ln1_b = (const float*)d_in[4];
    const float* Wqkv  = (const float*)d_in[5];
    const float* Wo    = (const float*)d_in[6];
    const float* ln2_g = (const float*)d_in[7];
    const float* ln2_b = (const float*)d_in[8];
    const float* W1    = (const float*)d_in[9];
    const float* W2    = (const float*)d_in[10];
    const float* lnf_g = (const float*)d_in[11];
    const float* lnf_b = (const float*)d_in[12];
    const float* Wc1   = (const float*)d_in[13];
    const float* bc1   = (const float*)d_in[14];
    const float* Wc2   = (const float*)d_in[15];
    const float* bc2   = (const float*)d_in[16];
    float* out = (float*)d_out;

    float *x, *h, *qkv, *mean, *t;
    __nv_bfloat16 *a3s, *a3f, *wqkv3, *wo3, *w13, *w23;
    cudaGetSymbolAddress((void**)&x,    g_x);
    cudaGetSymbolAddress((void**)&h,    g_h);
    cudaGetSymbolAddress((void**)&qkv,  g_qkv);
    cudaGetSymbolAddress((void**)&mean, g_mean);
    cudaGetSymbolAddress((void**)&t,    g_t);
    cudaGetSymbolAddress((void**)&a3s,   g_a3s);
    cudaGetSymbolAddress((void**)&a3f,   g_a3f);
    cudaGetSymbolAddress((void**)&wqkv3, g_wqkv3);
    cudaGetSymbolAddress((void**)&wo3,   g_wo3);
    cudaGetSymbolAddress((void**)&w13,   g_w13);
    cudaGetSymbolAddress((void**)&w23,   g_w23);

    cudaFuncSetAttribute(bgemm_kernel<0>,
                         cudaFuncAttributeMaxDynamicSharedMemorySize, BG_SMEM);
    cudaFuncSetAttribute(bgemm_kernel<1>,
                         cudaFuncAttributeMaxDynamicSharedMemorySize, BG_SMEM);
    cudaFuncSetAttribute(bgemm_kernel<2>,
                         cudaFuncAttributeMaxDynamicSharedMemorySize, BG_SMEM);

    embed_kernel<<<(BS * D) / 256, 256>>>(ids, emb, x);

    for (int l = 0; l < LAYERS; l++) {
        // attention block
        ln_kernel<1><<<BS, 256>>>(x, ln1_g + (size_t)l * D, ln1_b + (size_t)l * D,
                                  nullptr, a3s);
        convw_kernel<<<dim3(TD / 32, D / 32), dim3(32, 8)>>>(
            Wqkv + (size_t)l * D * TD, wqkv3, D, TD);
        bgemm_kernel<0><<<dim3(BS / 128, TD / 128), 256, BG_SMEM>>>(
            a3s, wqkv3, qkv, nullptr, BS, TD, 3 * D);
        attn_kernel<<<dim3(SEQ / 8, H, BATCH), 256>>>(qkv, amask, a3s);
        convw_kernel<<<dim3(D / 32, D / 32), dim3(32, 8)>>>(
            Wo + (size_t)l * D * D, wo3, D, D);
        bgemm_kernel<1><<<dim3(BS / 128, D / 128), 256, BG_SMEM>>>(
            a3s, wo3, x, nullptr, BS, D, 3 * D);
        // mlp block
        ln_kernel<1><<<BS, 256>>>(x, ln2_g + (size_t)l * D, ln2_b + (size_t)l * D,
                                  nullptr, a3s);
        convw_kernel<<<dim3(FF / 32, D / 32), dim3(32, 8)>>>(
            W1 + (size_t)l * D * FF, w13, D, FF);
        bgemm_kernel<2><<<dim3(BS / 128, FF / 128), 256, BG_SMEM>>>(
            a3s, w13, nullptr, a3f, BS, FF, 3 * D);
        convw_kernel<<<dim3(D / 32, FF / 32), dim3(32, 8)>>>(
            W2 + (size_t)l * FF * D, w23, FF, D);
        bgemm_kernel<1><<<dim3(BS / 128, D / 128), 256, BG_SMEM>>>(
            a3f, w23, x, nullptr, BS, D, 3 * FF);
    }

    ln_kernel<0><<<BS, 256>>>(x, lnf_g, lnf_b, h, nullptr);
    meanpool_kernel<<<(BATCH * D) / 256, 256>>>(h, amask, mean);
    head1_kernel<<<(BATCH * D) / 256, 256>>>(mean, Wc1, bc1, t);
    head2_kernel<<<1, 256>>>(t, Wc2, bc2, out);
}